// round 10
// baseline (speedup 1.0000x reference)
#include <cuda_runtime.h>

// LSTM: B=4096, T=512, I=3, H=32, C=3
// R8: occupancy release. NB=2 batches/warp -> 2048 one-warp blocks.
//     W_hh loaded GMEM->regs directly (no 16KB SMEM staging; static smem ~1.8KB
//     so SMEM never limits blocks/SM). __launch_bounds__(32,12) caps regs at 170
//     -> 3 warps/SMSP resident. Inner math identical to R6 (fp32x2 FMA,
//     duplicated-h broadcast LDS, folded 0.5 sigmoid scale, MUFU.TANH).

#define FULL_MASK 0xffffffffu
typedef unsigned long long ull;

constexpr int B_DIM  = 4096;
constexpr int T_DIM  = 512;
constexpr int H_DIM  = 32;
constexpr int NB     = 2;    // batches per warp (= per block)
constexpr int NTHREADS = 32; // one warp per block
constexpr int CHUNK  = 32;   // timesteps of x staged per phase

__device__ __forceinline__ float tanh_fast(float x) {
    float y;
    asm("tanh.approx.f32 %0, %1;" : "=f"(y) : "f"(x));
    return y;
}
__device__ __forceinline__ ull pack2(float lo, float hi) {
    ull r;
    asm("mov.b64 %0, {%1, %2};"
        : "=l"(r) : "r"(__float_as_uint(lo)), "r"(__float_as_uint(hi)));
    return r;
}
__device__ __forceinline__ void unpack2(ull v, float& lo, float& hi) {
    unsigned int a, b;
    asm("mov.b64 {%0, %1}, %2;" : "=r"(a), "=r"(b) : "l"(v));
    lo = __uint_as_float(a);
    hi = __uint_as_float(b);
}
__device__ __forceinline__ void fma2(ull& acc, ull a, ull b) {
    asm("fma.rn.f32x2 %0, %1, %2, %0;" : "+l"(acc) : "l"(a), "l"(b));
}

__global__ void __launch_bounds__(NTHREADS, 12)
lstm_fused_kernel(const float* __restrict__ x,      // (B,T,3)
                  const float* __restrict__ W_ih,   // (128,3)
                  const float* __restrict__ W_hh,   // (128,32)
                  const float* __restrict__ b_ih,   // (128,)
                  const float* __restrict__ b_hh,   // (128,)
                  const float* __restrict__ W_fc,   // (3,32)
                  const float* __restrict__ b_fc,   // (3,)
                  float* __restrict__ out)          // (B,3)
{
    // x chunk staging: 2 batches * 24 float4 = 48 float4 (768 B)
    __shared__ float4 sx4[NB * (CHUNK * 3 / 4)];
    // duplicated h, double-buffered: shb[pb][j] = {h0,h0,h1,h1} (1 KB)
    __shared__ float4 shb[2][H_DIM];

    const int lane = threadIdx.x & 31;
    const int b0   = blockIdx.x * NB;

    // ---- W_hh straight into registers, permuted + 0.5-scaled (i,f,o) ----
    // w01[j] = {W_hh[lane,j]*0.5,      W_hh[32+lane,j]*0.5}   (gates i,f)
    // w23[j] = {W_hh[64+lane,j],       W_hh[96+lane,j]*0.5}   (gates g,o)
    ull w01[H_DIM], w23[H_DIM];
    {
        const float* r0 = W_hh + (0 * 32 + lane) * H_DIM;
        const float* r1 = W_hh + (1 * 32 + lane) * H_DIM;
        const float* r2 = W_hh + (2 * 32 + lane) * H_DIM;
        const float* r3 = W_hh + (3 * 32 + lane) * H_DIM;
#pragma unroll
        for (int j = 0; j < H_DIM; j++) {
            w01[j] = pack2(r0[j] * 0.5f, r1[j] * 0.5f);
            w23[j] = pack2(r2[j],        r3[j] * 0.5f);
        }
    }

    // ---- per-lane input weights + combined bias (scaled) ----
    float wih[4][3];
    float bias[4];
#pragma unroll
    for (int q = 0; q < 4; q++) {
        int row = q * 32 + lane;
        float s = (q == 2) ? 1.0f : 0.5f;
        wih[q][0] = W_ih[row * 3 + 0] * s;
        wih[q][1] = W_ih[row * 3 + 1] * s;
        wih[q][2] = W_ih[row * 3 + 2] * s;
        bias[q]   = (b_ih[row] + b_hh[row]) * s;
    }

    // init h buffer 0 to zeros
    shb[0][lane] = make_float4(0.f, 0.f, 0.f, 0.f);
    __syncwarp();

    float c0 = 0.0f, c1 = 0.0f;
    float h0 = 0.0f, h1 = 0.0f;

    const float* sxf = reinterpret_cast<const float*>(sx4);
    const float4* xv = reinterpret_cast<const float4*>(x);
    int pb = 0;

    for (int tc = 0; tc < T_DIM; tc += CHUNK) {
        // ---- stage x chunk: 2 batches * 24 float4 = 48 float4 ----
        {
            const int cbase = (tc / CHUNK) * 24;   // = tc*3/4
#pragma unroll
            for (int k = 0; k < 2; k++) {
                int idx = lane + k * 32;           // 0..63
                if (idx < 48) {
                    int n = idx / 24, rem = idx % 24;
                    sx4[idx] = xv[(size_t)(b0 + n) * (T_DIM * 3 / 4) + cbase + rem];
                }
            }
        }
        __syncwarp();

#pragma unroll 1
        for (int tt = 0; tt < CHUNK; tt++) {
            // ---- input projection (scalar broadcast x, pre-scaled weights) ----
            ull acc01[NB], acc23[NB];
#pragma unroll
            for (int n = 0; n < NB; n++) {
                float x0 = sxf[n * 96 + tt * 3 + 0];
                float x1 = sxf[n * 96 + tt * 3 + 1];
                float x2 = sxf[n * 96 + tt * 3 + 2];
                float a0 = fmaf(x2, wih[0][2], fmaf(x1, wih[0][1], fmaf(x0, wih[0][0], bias[0])));
                float a1 = fmaf(x2, wih[1][2], fmaf(x1, wih[1][1], fmaf(x0, wih[1][0], bias[1])));
                float a2 = fmaf(x2, wih[2][2], fmaf(x1, wih[2][1], fmaf(x0, wih[2][0], bias[2])));
                float a3 = fmaf(x2, wih[3][2], fmaf(x1, wih[3][1], fmaf(x0, wih[3][0], bias[3])));
                acc01[n] = pack2(a0, a1);
                acc23[n] = pack2(a2, a3);
            }

            // ---- recurrent matvec: weights in regs, h via broadcast LDS.128 ----
            {
                const ulonglong2* hb =
                    reinterpret_cast<const ulonglong2*>(&shb[pb][0]);
#pragma unroll
                for (int j = 0; j < H_DIM; j++) {
                    ulonglong2 ha = hb[j];           // {h0,h0} {h1,h1}
                    fma2(acc01[0], w01[j], ha.x);
                    fma2(acc23[0], w23[j], ha.x);
                    fma2(acc01[1], w01[j], ha.y);
                    fma2(acc23[1], w23[j], ha.y);
                }
            }

            // ---- gates + cell update (i,f,o pre-scaled by 0.5) ----
            {
                float ig, fg, gg, og;
                unpack2(acc01[0], ig, fg);
                unpack2(acc23[0], gg, og);
                ig = fmaf(0.5f, tanh_fast(ig), 0.5f);
                fg = fmaf(0.5f, tanh_fast(fg), 0.5f);
                gg = tanh_fast(gg);
                og = fmaf(0.5f, tanh_fast(og), 0.5f);
                c0 = fmaf(fg, c0, ig * gg);
                h0 = og * tanh_fast(c0);
            }
            {
                float ig, fg, gg, og;
                unpack2(acc01[1], ig, fg);
                unpack2(acc23[1], gg, og);
                ig = fmaf(0.5f, tanh_fast(ig), 0.5f);
                fg = fmaf(0.5f, tanh_fast(fg), 0.5f);
                gg = tanh_fast(gg);
                og = fmaf(0.5f, tanh_fast(og), 0.5f);
                c1 = fmaf(fg, c1, ig * gg);
                h1 = og * tanh_fast(c1);
            }

            // ---- publish duplicated h to the other buffer ----
            shb[pb ^ 1][lane] = make_float4(h0, h0, h1, h1);
            __syncwarp();
            pb ^= 1;
        }
    }

    // ---- final FC: out[b,c] = h . W_fc[c,:] + b_fc[c] ----
    const float wfc0 = W_fc[0 * H_DIM + lane];
    const float wfc1 = W_fc[1 * H_DIM + lane];
    const float wfc2 = W_fc[2 * H_DIM + lane];
#pragma unroll
    for (int n = 0; n < NB; n++) {
        float hn = (n == 0) ? h0 : h1;
        float v0 = hn * wfc0;
        float v1 = hn * wfc1;
        float v2 = hn * wfc2;
#pragma unroll
        for (int off = 16; off > 0; off >>= 1) {
            v0 += __shfl_xor_sync(FULL_MASK, v0, off);
            v1 += __shfl_xor_sync(FULL_MASK, v1, off);
            v2 += __shfl_xor_sync(FULL_MASK, v2, off);
        }
        if (lane == 0) {
            out[(b0 + n) * 3 + 0] = v0 + b_fc[0];
            out[(b0 + n) * 3 + 1] = v1 + b_fc[1];
            out[(b0 + n) * 3 + 2] = v2 + b_fc[2];
        }
    }
}

extern "C" void kernel_launch(void* const* d_in, const int* in_sizes, int n_in,
                              void* d_out, int out_size) {
    const float* x    = (const float*)d_in[0];
    const float* W_ih = (const float*)d_in[1];
    const float* W_hh = (const float*)d_in[2];
    const float* b_ih = (const float*)d_in[3];
    const float* b_hh = (const float*)d_in[4];
    const float* W_fc = (const float*)d_in[5];
    const float* b_fc = (const float*)d_in[6];
    float* out = (float*)d_out;

    const int grid = B_DIM / NB;  // 2048 one-warp blocks
    lstm_fused_kernel<<<grid, NTHREADS>>>(x, W_ih, W_hh, b_ih, b_hh, W_fc, b_fc, out);
}

// round 12
// speedup vs baseline: 1.5232x; 1.5232x over previous
#include <cuda_runtime.h>

// LSTM: B=4096, T=512, I=3, H=32, C=3
// R10 = R6 inner loop (NB=4, fp32x2 FMA, duplicated-h broadcast LDS,
//       folded 0.5 sigmoid scale, MUFU.TANH), with the 16KB SMEM weight-staging
//       buffer replaced by a direct GMEM->register W_hh load. Static SMEM ~3.5KB
//       -> residency becomes register-limited (2 warps/SMSP, 8 warps/SM).

#define FULL_MASK 0xffffffffu
typedef unsigned long long ull;

constexpr int B_DIM  = 4096;
constexpr int T_DIM  = 512;
constexpr int H_DIM  = 32;
constexpr int NB     = 4;    // batches per warp (= per block)
constexpr int NTHREADS = 32; // one warp per block
constexpr int CHUNK  = 32;   // timesteps of x staged per phase

__device__ __forceinline__ float tanh_fast(float x) {
    float y;
    asm("tanh.approx.f32 %0, %1;" : "=f"(y) : "f"(x));
    return y;
}
__device__ __forceinline__ ull pack2(float lo, float hi) {
    ull r;
    asm("mov.b64 %0, {%1, %2};"
        : "=l"(r) : "r"(__float_as_uint(lo)), "r"(__float_as_uint(hi)));
    return r;
}
__device__ __forceinline__ void unpack2(ull v, float& lo, float& hi) {
    unsigned int a, b;
    asm("mov.b64 {%0, %1}, %2;" : "=r"(a), "=r"(b) : "l"(v));
    lo = __uint_as_float(a);
    hi = __uint_as_float(b);
}
__device__ __forceinline__ void fma2(ull& acc, ull a, ull b) {
    asm("fma.rn.f32x2 %0, %1, %2, %0;" : "+l"(acc) : "l"(a), "l"(b));
}

__global__ void __launch_bounds__(NTHREADS)
lstm_fused_kernel(const float* __restrict__ x,      // (B,T,3)
                  const float* __restrict__ W_ih,   // (128,3)
                  const float* __restrict__ W_hh,   // (128,32)
                  const float* __restrict__ b_ih,   // (128,)
                  const float* __restrict__ b_hh,   // (128,)
                  const float* __restrict__ W_fc,   // (3,32)
                  const float* __restrict__ b_fc,   // (3,)
                  float* __restrict__ out)          // (B,3)
{
    // x chunk staging: 4 batches * 24 float4 = 96 float4 (1.5 KB)
    __shared__ float4 sx4[NB * (CHUNK * 3 / 4)];
    // duplicated h, double-buffered: shb[pb][j][0]={h0,h0,h1,h1}, [1]={h2,h2,h3,h3} (2 KB)
    __shared__ float4 shb[2][H_DIM][2];

    const int lane = threadIdx.x & 31;
    const int b0   = blockIdx.x * NB;

    // ---- W_hh straight into registers, permuted + 0.5-scaled (i,f,o) ----
    // w01[j] = {W_hh[lane,j]*0.5,   W_hh[32+lane,j]*0.5}   (gates i,f)
    // w23[j] = {W_hh[64+lane,j],    W_hh[96+lane,j]*0.5}   (gates g,o)
    ull w01[H_DIM], w23[H_DIM];
    {
        const float* r0 = W_hh + (0 * 32 + lane) * H_DIM;
        const float* r1 = W_hh + (1 * 32 + lane) * H_DIM;
        const float* r2 = W_hh + (2 * 32 + lane) * H_DIM;
        const float* r3 = W_hh + (3 * 32 + lane) * H_DIM;
#pragma unroll
        for (int j = 0; j < H_DIM; j++) {
            w01[j] = pack2(r0[j] * 0.5f, r1[j] * 0.5f);
            w23[j] = pack2(r2[j],        r3[j] * 0.5f);
        }
    }

    // ---- per-lane input weights + combined bias (scaled) ----
    float wih[4][3];
    float bias[4];
#pragma unroll
    for (int q = 0; q < 4; q++) {
        int row = q * 32 + lane;
        float s = (q == 2) ? 1.0f : 0.5f;
        wih[q][0] = W_ih[row * 3 + 0] * s;
        wih[q][1] = W_ih[row * 3 + 1] * s;
        wih[q][2] = W_ih[row * 3 + 2] * s;
        bias[q]   = (b_ih[row] + b_hh[row]) * s;
    }

    // init h buffer 0 to zeros
    shb[0][lane][0] = make_float4(0.f, 0.f, 0.f, 0.f);
    shb[0][lane][1] = make_float4(0.f, 0.f, 0.f, 0.f);
    __syncwarp();

    float h[NB], c[NB];
#pragma unroll
    for (int n = 0; n < NB; n++) { h[n] = 0.0f; c[n] = 0.0f; }

    const float* sxf = reinterpret_cast<const float*>(sx4);
    const float4* xv = reinterpret_cast<const float4*>(x);
    int pb = 0;

    for (int tc = 0; tc < T_DIM; tc += CHUNK) {
        // ---- stage x chunk: 4 batches * 24 float4 ----
        {
            const int cbase = (tc / CHUNK) * 24;  // = tc*3/4
#pragma unroll
            for (int k = 0; k < 3; k++) {
                int idx = lane + k * 32;          // 0..95
                int n = idx / 24, rem = idx % 24;
                sx4[idx] = xv[(size_t)(b0 + n) * (T_DIM * 3 / 4) + cbase + rem];
            }
        }
        __syncwarp();

#pragma unroll 1
        for (int tt = 0; tt < CHUNK; tt++) {
            // ---- input projection (scalar broadcast x, pre-scaled weights) ----
            ull acc01[NB], acc23[NB];
#pragma unroll
            for (int n = 0; n < NB; n++) {
                float x0 = sxf[n * 96 + tt * 3 + 0];
                float x1 = sxf[n * 96 + tt * 3 + 1];
                float x2 = sxf[n * 96 + tt * 3 + 2];
                float a0 = fmaf(x2, wih[0][2], fmaf(x1, wih[0][1], fmaf(x0, wih[0][0], bias[0])));
                float a1 = fmaf(x2, wih[1][2], fmaf(x1, wih[1][1], fmaf(x0, wih[1][0], bias[1])));
                float a2 = fmaf(x2, wih[2][2], fmaf(x1, wih[2][1], fmaf(x0, wih[2][0], bias[2])));
                float a3 = fmaf(x2, wih[3][2], fmaf(x1, wih[3][1], fmaf(x0, wih[3][0], bias[3])));
                acc01[n] = pack2(a0, a1);
                acc23[n] = pack2(a2, a3);
            }

            // ---- recurrent matvec: weights in regs, h via broadcast LDS.128 ----
            {
                const ulonglong2* hb =
                    reinterpret_cast<const ulonglong2*>(&shb[pb][0][0]);
#pragma unroll
                for (int j = 0; j < H_DIM; j++) {
                    ulonglong2 ha = hb[j * 2 + 0];  // {h0,h0} {h1,h1}
                    ulonglong2 hc = hb[j * 2 + 1];  // {h2,h2} {h3,h3}
                    fma2(acc01[0], w01[j], ha.x); fma2(acc23[0], w23[j], ha.x);
                    fma2(acc01[1], w01[j], ha.y); fma2(acc23[1], w23[j], ha.y);
                    fma2(acc01[2], w01[j], hc.x); fma2(acc23[2], w23[j], hc.x);
                    fma2(acc01[3], w01[j], hc.y); fma2(acc23[3], w23[j], hc.y);
                }
            }

            // ---- gates + cell update (i,f,o pre-scaled by 0.5) ----
#pragma unroll
            for (int n = 0; n < NB; n++) {
                float ig, fg, gg, og;
                unpack2(acc01[n], ig, fg);
                unpack2(acc23[n], gg, og);
                ig = fmaf(0.5f, tanh_fast(ig), 0.5f);
                fg = fmaf(0.5f, tanh_fast(fg), 0.5f);
                gg = tanh_fast(gg);
                og = fmaf(0.5f, tanh_fast(og), 0.5f);
                c[n] = fmaf(fg, c[n], ig * gg);
                h[n] = og * tanh_fast(c[n]);
            }

            // ---- publish duplicated h to the other buffer ----
            shb[pb ^ 1][lane][0] = make_float4(h[0], h[0], h[1], h[1]);
            shb[pb ^ 1][lane][1] = make_float4(h[2], h[2], h[3], h[3]);
            __syncwarp();
            pb ^= 1;
        }
    }

    // ---- final FC: out[b,c] = h . W_fc[c,:] + b_fc[c] ----
    const float wfc0 = W_fc[0 * H_DIM + lane];
    const float wfc1 = W_fc[1 * H_DIM + lane];
    const float wfc2 = W_fc[2 * H_DIM + lane];
#pragma unroll
    for (int n = 0; n < NB; n++) {
        float v0 = h[n] * wfc0;
        float v1 = h[n] * wfc1;
        float v2 = h[n] * wfc2;
#pragma unroll
        for (int off = 16; off > 0; off >>= 1) {
            v0 += __shfl_xor_sync(FULL_MASK, v0, off);
            v1 += __shfl_xor_sync(FULL_MASK, v1, off);
            v2 += __shfl_xor_sync(FULL_MASK, v2, off);
        }
        if (lane == 0) {
            out[(b0 + n) * 3 + 0] = v0 + b_fc[0];
            out[(b0 + n) * 3 + 1] = v1 + b_fc[1];
            out[(b0 + n) * 3 + 2] = v2 + b_fc[2];
        }
    }
}

extern "C" void kernel_launch(void* const* d_in, const int* in_sizes, int n_in,
                              void* d_out, int out_size) {
    const float* x    = (const float*)d_in[0];
    const float* W_ih = (const float*)d_in[1];
    const float* W_hh = (const float*)d_in[2];
    const float* b_ih = (const float*)d_in[3];
    const float* b_hh = (const float*)d_in[4];
    const float* W_fc = (const float*)d_in[5];
    const float* b_fc = (const float*)d_in[6];
    float* out = (float*)d_out;

    const int grid = B_DIM / NB;  // 1024 one-warp blocks
    lstm_fused_kernel<<<grid, NTHREADS>>>(x, W_ih, W_hh, b_ih, b_hh, W_fc, b_fc, out);
}